// round 16
// baseline (speedup 1.0000x reference)
#include <cuda_runtime.h>
#include <cuda_fp16.h>
#include <cstdint>

// ---------------------------------------------------------------------------
// Problem dims (fixed)
// ---------------------------------------------------------------------------
#define M_DIM 16384
#define D_DIM 1024

// GEMM tiling (shared by both kernels)
#define BM 128
#define BN 128
#define BK 64                        // fp16 elements per K-stage (=128B rows)
#define NSTAGES (D_DIM / BK)         // 16
#define NBUF 3
#define NTH 256                      // 8 warps (2x4 grid, 64x32 warp tiles)

// Hidden-layer smem: 2 planes (A,B), 3 buffers -> 96KB -> 2 CTAs/SM
#define A_SZ (BM * 128)              // 16384
#define OFF_A 0
#define OFF_B (A_SZ)
#define STAGE_H (2 * A_SZ)           // 32768
#define SMEM_H (NBUF * STAGE_H)      // 98304

// Final-GEMM smem: 4 planes (Ah,Al,Bh,Bl), 3 buffers -> 192KB -> 1 CTA/SM
#define OFF_AH 0
#define OFF_AL (A_SZ)
#define OFF_BH (2 * A_SZ)
#define OFF_BL (3 * A_SZ)
#define STAGE_F (4 * A_SZ)           // 65536
#define SMEM_F (NBUF * STAGE_F)      // 196608

// ---------------------------------------------------------------------------
// Scratch (__device__ globals; no allocation allowed)
// g_x16 is reused as the A5-lo plane after layer 1 consumes it.
// ---------------------------------------------------------------------------
__device__ __align__(1024) __half g_x16[(size_t)M_DIM * D_DIM];
__device__ __align__(1024) __half g_a0[(size_t)M_DIM * D_DIM];
__device__ __align__(1024) __half g_a1[(size_t)M_DIM * D_DIM];
__device__ __align__(1024) __half g_ws[(size_t)4 * D_DIM * D_DIM];
__device__ __align__(1024) __half g_woh[(size_t)D_DIM * D_DIM];
__device__ __align__(1024) __half g_wol[(size_t)D_DIM * D_DIM];
__device__ float g_rowsum[M_DIM];

// ---------------------------------------------------------------------------
// PTX helpers (all baseline compute_80-level)
// ---------------------------------------------------------------------------
__device__ __forceinline__ uint32_t smem_u32(const void* p) {
    uint32_t a;
    asm("{ .reg .u64 t; cvta.to.shared.u64 t, %1; cvt.u32.u64 %0, t; }"
        : "=r"(a) : "l"(p));
    return a;
}
__device__ __forceinline__ void cpa16(uint32_t dst, const void* src) {
    asm volatile("cp.async.cg.shared.global [%0], [%1], 16;" :: "r"(dst), "l"(src));
}
#define CP_COMMIT() asm volatile("cp.async.commit_group;" ::: "memory")
#define CP_WAIT1()  asm volatile("cp.async.wait_group 1;" ::: "memory")

__device__ __forceinline__ uint32_t swz(uint32_t off) {
    return off ^ ((off >> 3) & 0x70);
}
__device__ __forceinline__ void ldmx4(uint32_t* r, uint32_t addr) {
    asm volatile("ldmatrix.sync.aligned.m8n8.x4.shared.b16 {%0,%1,%2,%3}, [%4];"
                 : "=r"(r[0]), "=r"(r[1]), "=r"(r[2]), "=r"(r[3]) : "r"(addr));
}
__device__ __forceinline__ void mma16816(float* c, const uint32_t* a,
                                         const uint32_t* b) {
    asm volatile(
        "mma.sync.aligned.m16n8k16.row.col.f32.f16.f16.f32 "
        "{%0,%1,%2,%3}, {%4,%5,%6,%7}, {%8,%9}, {%0,%1,%2,%3};"
        : "+f"(c[0]), "+f"(c[1]), "+f"(c[2]), "+f"(c[3])
        : "r"(a[0]), "r"(a[1]), "r"(a[2]), "r"(a[3]), "r"(b[0]), "r"(b[1]));
}

// ---------------------------------------------------------------------------
// Pre-processing kernels
// ---------------------------------------------------------------------------
__global__ void conv_kernel(const float* __restrict__ s,
                            __half* __restrict__ h, int n4) {
    int i = blockIdx.x * blockDim.x + threadIdx.x;
    if (i >= n4) return;
    float4 v = reinterpret_cast<const float4*>(s)[i];
    reinterpret_cast<__half2*>(h)[i * 2 + 0] = __floats2half2_rn(v.x, v.y);
    reinterpret_cast<__half2*>(h)[i * 2 + 1] = __floats2half2_rn(v.z, v.w);
}

// fp32 -> fp16 hi/lo split (for Wo)
__global__ void conv_split(const float* __restrict__ s,
                           __half* __restrict__ h, __half* __restrict__ l,
                           int n4) {
    int i = blockIdx.x * blockDim.x + threadIdx.x;
    if (i >= n4) return;
    float4 v = reinterpret_cast<const float4*>(s)[i];
    __half h0 = __float2half_rn(v.x), h1 = __float2half_rn(v.y);
    __half h2 = __float2half_rn(v.z), h3 = __float2half_rn(v.w);
    __half l0 = __float2half_rn(v.x - __half2float(h0));
    __half l1 = __float2half_rn(v.y - __half2float(h1));
    __half l2 = __float2half_rn(v.z - __half2float(h2));
    __half l3 = __float2half_rn(v.w - __half2float(h3));
    reinterpret_cast<__half2*>(h)[i * 2 + 0] = __half2(h0, h1);
    reinterpret_cast<__half2*>(h)[i * 2 + 1] = __half2(h2, h3);
    reinterpret_cast<__half2*>(l)[i * 2 + 0] = __half2(l0, l1);
    reinterpret_cast<__half2*>(l)[i * 2 + 1] = __half2(l2, l3);
}

__global__ void convx_rowsum(const float* __restrict__ x,
                             __half* __restrict__ xh,
                             float* __restrict__ rs) {
    int row  = blockIdx.x * 8 + (threadIdx.x >> 5);
    int lane = threadIdx.x & 31;
    const float4* xr = reinterpret_cast<const float4*>(x + (size_t)row * D_DIM);
    __half2* dh = reinterpret_cast<__half2*>(xh + (size_t)row * D_DIM);
    float s = 0.f;
#pragma unroll
    for (int i = 0; i < 8; i++) {
        float4 v = xr[lane + i * 32];
        s += v.x + v.y + v.z + v.w;
        dh[(lane + i * 32) * 2 + 0] = __floats2half2_rn(v.x, v.y);
        dh[(lane + i * 32) * 2 + 1] = __floats2half2_rn(v.z, v.w);
    }
#pragma unroll
    for (int o = 16; o > 0; o >>= 1) s += __shfl_xor_sync(0xffffffffu, s, o);
    if (lane == 0) rs[row] = s;
}

// ---------------------------------------------------------------------------
// Hidden-layer GEMM: single-term fp16, 2 CTAs/SM.
// MODE 0: relu(acc+b) -> fp16
// MODE 1: (relu(acc+b)+relu(x*rs))*0.5 -> fp16 hi (Oh) + fp16 lo (Ol)
// ---------------------------------------------------------------------------
template <int MODE>
__global__ __launch_bounds__(NTH, 2)
void gemm_hid(const __half* __restrict__ A, const __half* __restrict__ W,
              const float* __restrict__ bias,
              __half* __restrict__ Oh, __half* __restrict__ Ol,
              const float* __restrict__ x, const float* __restrict__ rowsum)
{
    extern __shared__ __align__(1024) char smem_raw[];
    const uint32_t sb = smem_u32(smem_raw);

    const int tid  = threadIdx.x;
    const int wid  = tid >> 5;
    const int lane = tid & 31;
    const int wm   = wid >> 2;          // 0..1  (64 rows each)
    const int wn   = wid & 3;           // 0..3  (32 cols each)
    const int n0   = blockIdx.x * BN;
    const int m0   = blockIdx.y * BM;

    const int lc = tid & 7;
    uint32_t swo[4], gaO[4], gbO[4];
#pragma unroll
    for (int i = 0; i < 4; i++) {
        int r = (tid >> 3) + i * 32;
        swo[i] = swz((uint32_t)(r * 128 + lc * 16));
        gaO[i] = (uint32_t)(m0 + r) * D_DIM + lc * 8;
        gbO[i] = (uint32_t)(n0 + r) * D_DIM + lc * 8;
    }

    auto load_stage = [&](int s) {
        const uint32_t base = sb + (uint32_t)(s % NBUF) * STAGE_H;
        const uint32_t kt = (uint32_t)s * BK;
#pragma unroll
        for (int i = 0; i < 4; i++) {
            cpa16(base + OFF_A + swo[i], A + gaO[i] + kt);
            cpa16(base + OFF_B + swo[i], W + gbO[i] + kt);
        }
    };

    float acc[4][4][4];
#pragma unroll
    for (int i = 0; i < 4; i++)
#pragma unroll
        for (int j = 0; j < 4; j++)
#pragma unroll
            for (int q = 0; q < 4; q++) acc[i][j][q] = 0.f;

    load_stage(0); CP_COMMIT();
    load_stage(1); CP_COMMIT();

    const uint32_t a_row = wm * 64 + (lane & 15);
    const uint32_t a_k   = (uint32_t)(lane >> 4) * 8;
    const uint32_t b_row = wn * 32 + ((uint32_t)(lane >> 4) * 8) + (lane & 7);
    const uint32_t b_k   = (uint32_t)((lane >> 3) & 1) * 8;

#pragma unroll 1
    for (int s = 0; s < NSTAGES; s++) {
        CP_WAIT1();
        __syncthreads();

        const uint32_t base = sb + (uint32_t)(s % NBUF) * STAGE_H;
#pragma unroll
        for (int ks = 0; ks < 4; ks++) {
            const uint32_t kk = ks * 16;
            uint32_t ah[4][4], bh[2][4];
#pragma unroll
            for (int mt = 0; mt < 4; mt++) {
                uint32_t sw = swz((a_row + mt * 16) * 128 + (kk + a_k) * 2);
                ldmx4(ah[mt], base + OFF_A + sw);
            }
#pragma unroll
            for (int nb = 0; nb < 2; nb++) {
                uint32_t sw = swz((b_row + nb * 16) * 128 + (kk + b_k) * 2);
                ldmx4(bh[nb], base + OFF_B + sw);
            }
#pragma unroll
            for (int mt = 0; mt < 4; mt++)
#pragma unroll
                for (int nt = 0; nt < 4; nt++)
                    mma16816(acc[mt][nt], ah[mt], &bh[nt >> 1][(nt & 1) * 2]);
        }

        if (s + 2 < NSTAGES) { load_stage(s + 2); CP_COMMIT(); }
    }

    // ---- epilogue ----
    const int qrow = lane >> 2;
    const int qcol = (lane & 3) * 2;
#pragma unroll
    for (int mt = 0; mt < 4; mt++) {
#pragma unroll
        for (int half = 0; half < 2; half++) {
            const int gm = m0 + wm * 64 + mt * 16 + qrow + half * 8;
            float rsv = 0.f;
            if (MODE == 1) rsv = rowsum[gm];
#pragma unroll
            for (int nt = 0; nt < 4; nt++) {
                const int gn = n0 + wn * 32 + nt * 8 + qcol;
                const float2 bv = *reinterpret_cast<const float2*>(bias + gn);
                float v0 = fmaxf(acc[mt][nt][half * 2 + 0] + bv.x, 0.f);
                float v1 = fmaxf(acc[mt][nt][half * 2 + 1] + bv.y, 0.f);
                if (MODE == 1) {
                    const float2 xv = *reinterpret_cast<const float2*>(
                        x + (size_t)gm * D_DIM + gn);
                    v0 = (v0 + fmaxf(xv.x * rsv, 0.f)) * 0.5f;
                    v1 = (v1 + fmaxf(xv.y * rsv, 0.f)) * 0.5f;
                    __half h0 = __float2half_rn(v0), h1 = __float2half_rn(v1);
                    __half l0 = __float2half_rn(v0 - __half2float(h0));
                    __half l1 = __float2half_rn(v1 - __half2float(h1));
                    *reinterpret_cast<__half2*>(Oh + (size_t)gm * D_DIM + gn) =
                        __half2(h0, h1);
                    *reinterpret_cast<__half2*>(Ol + (size_t)gm * D_DIM + gn) =
                        __half2(l0, l1);
                } else {
                    *reinterpret_cast<__half2*>(Oh + (size_t)gm * D_DIM + gn) =
                        __floats2half2_rn(v0, v1);
                }
            }
        }
    }
}

// ---------------------------------------------------------------------------
// Final projection GEMM: 3-term split fp16 (AhWh + AlWh + AhWl), fp32 out.
// 4 smem planes, NBUF=3, 1 CTA/SM (R9-proven structure).
// ---------------------------------------------------------------------------
__global__ __launch_bounds__(NTH, 1)
void gemm_fin(const __half* __restrict__ Ah, const __half* __restrict__ Al,
              const __half* __restrict__ Wh, const __half* __restrict__ Wl,
              const float* __restrict__ bias, float* __restrict__ Of)
{
    extern __shared__ __align__(1024) char smem_raw[];
    const uint32_t sb = smem_u32(smem_raw);

    const int tid  = threadIdx.x;
    const int wid  = tid >> 5;
    const int lane = tid & 31;
    const int wm   = wid >> 2;
    const int wn   = wid & 3;
    const int n0   = blockIdx.x * BN;
    const int m0   = blockIdx.y * BM;

    const int lc = tid & 7;
    uint32_t swo[4], gaO[4], gbO[4];
#pragma unroll
    for (int i = 0; i < 4; i++) {
        int r = (tid >> 3) + i * 32;
        swo[i] = swz((uint32_t)(r * 128 + lc * 16));
        gaO[i] = (uint32_t)(m0 + r) * D_DIM + lc * 8;
        gbO[i] = (uint32_t)(n0 + r) * D_DIM + lc * 8;
    }

    auto load_stage = [&](int s) {
        const uint32_t base = sb + (uint32_t)(s % NBUF) * STAGE_F;
        const uint32_t kt = (uint32_t)s * BK;
#pragma unroll
        for (int i = 0; i < 4; i++) {
            cpa16(base + OFF_AH + swo[i], Ah + gaO[i] + kt);
            cpa16(base + OFF_AL + swo[i], Al + gaO[i] + kt);
            cpa16(base + OFF_BH + swo[i], Wh + gbO[i] + kt);
            cpa16(base + OFF_BL + swo[i], Wl + gbO[i] + kt);
        }
    };

    float acc[4][4][4];
#pragma unroll
    for (int i = 0; i < 4; i++)
#pragma unroll
        for (int j = 0; j < 4; j++)
#pragma unroll
            for (int q = 0; q < 4; q++) acc[i][j][q] = 0.f;

    load_stage(0); CP_COMMIT();
    load_stage(1); CP_COMMIT();

    const uint32_t a_row = wm * 64 + (lane & 15);
    const uint32_t a_k   = (uint32_t)(lane >> 4) * 8;
    const uint32_t b_row = wn * 32 + ((uint32_t)(lane >> 4) * 8) + (lane & 7);
    const uint32_t b_k   = (uint32_t)((lane >> 3) & 1) * 8;

#pragma unroll 1
    for (int s = 0; s < NSTAGES; s++) {
        CP_WAIT1();
        __syncthreads();

        const uint32_t base = sb + (uint32_t)(s % NBUF) * STAGE_F;
#pragma unroll
        for (int ks = 0; ks < 4; ks++) {
            const uint32_t kk = ks * 16;
            uint32_t ah[4][4], al[4][4], bh[2][4], bl[2][4];
#pragma unroll
            for (int mt = 0; mt < 4; mt++) {
                uint32_t sw = swz((a_row + mt * 16) * 128 + (kk + a_k) * 2);
                ldmx4(ah[mt], base + OFF_AH + sw);
                ldmx4(al[mt], base + OFF_AL + sw);
            }
#pragma unroll
            for (int nb = 0; nb < 2; nb++) {
                uint32_t sw = swz((b_row + nb * 16) * 128 + (kk + b_k) * 2);
                ldmx4(bh[nb], base + OFF_BH + sw);
                ldmx4(bl[nb], base + OFF_BL + sw);
            }
#pragma unroll
            for (int mt = 0; mt < 4; mt++)
#pragma unroll
                for (int nt = 0; nt < 4; nt++) {
                    const uint32_t* bhp = &bh[nt >> 1][(nt & 1) * 2];
                    const uint32_t* blp = &bl[nt >> 1][(nt & 1) * 2];
                    mma16816(acc[mt][nt], ah[mt], bhp);
                    mma16816(acc[mt][nt], al[mt], bhp);
                    mma16816(acc[mt][nt], ah[mt], blp);
                }
        }

        if (s + 2 < NSTAGES) { load_stage(s + 2); CP_COMMIT(); }
    }

    // ---- epilogue: fp32 out ----
    const int qrow = lane >> 2;
    const int qcol = (lane & 3) * 2;
#pragma unroll
    for (int mt = 0; mt < 4; mt++) {
#pragma unroll
        for (int half = 0; half < 2; half++) {
            const int gm = m0 + wm * 64 + mt * 16 + qrow + half * 8;
#pragma unroll
            for (int nt = 0; nt < 4; nt++) {
                const int gn = n0 + wn * 32 + nt * 8 + qcol;
                const float2 bv = *reinterpret_cast<const float2*>(bias + gn);
                *reinterpret_cast<float2*>(Of + (size_t)gm * D_DIM + gn) =
                    make_float2(acc[mt][nt][half * 2 + 0] + bv.x,
                                acc[mt][nt][half * 2 + 1] + bv.y);
            }
        }
    }
}

// ---------------------------------------------------------------------------
// Launch
// ---------------------------------------------------------------------------
extern "C" void kernel_launch(void* const* d_in, const int* in_sizes, int n_in,
                              void* d_out, int out_size) {
    const float* x  = (const float*)d_in[0];
    const float* Ws = (const float*)d_in[1];   // (4, D, D)
    const float* bs = (const float*)d_in[2];   // (4, D)
    const float* Wo = (const float*)d_in[3];   // (D, D)
    const float* bo = (const float*)d_in[4];   // (D,)
    float* out = (float*)d_out;

    __half *x16, *a0, *a1, *ws, *woh, *wol;
    float* rs;
    cudaGetSymbolAddress((void**)&x16, g_x16);
    cudaGetSymbolAddress((void**)&a0,  g_a0);
    cudaGetSymbolAddress((void**)&a1,  g_a1);
    cudaGetSymbolAddress((void**)&ws,  g_ws);
    cudaGetSymbolAddress((void**)&woh, g_woh);
    cudaGetSymbolAddress((void**)&wol, g_wol);
    cudaGetSymbolAddress((void**)&rs,  g_rowsum);

    cudaFuncSetAttribute(gemm_hid<0>, cudaFuncAttributeMaxDynamicSharedMemorySize, SMEM_H);
    cudaFuncSetAttribute(gemm_hid<1>, cudaFuncAttributeMaxDynamicSharedMemorySize, SMEM_H);
    cudaFuncSetAttribute(gemm_fin,    cudaFuncAttributeMaxDynamicSharedMemorySize, SMEM_F);

    const size_t DD = (size_t)D_DIM * D_DIM;

    convx_rowsum<<<M_DIM / 8, 256>>>(x, x16, rs);
    conv_kernel<<<(int)(4 * DD / 4 / 256), 256>>>(Ws, ws, (int)(4 * DD / 4));
    conv_split<<<(int)(DD / 4 / 256), 256>>>(Wo, woh, wol, (int)(DD / 4));

    dim3 grid(D_DIM / BN, M_DIM / BM);   // (8, 128)

    // Hidden layers (single-term fp16, 2 CTAs/SM)
    gemm_hid<0><<<grid, NTH, SMEM_H>>>(x16, ws + 0 * DD, bs + 0 * D_DIM,
                                       a0, nullptr, nullptr, nullptr);
    gemm_hid<0><<<grid, NTH, SMEM_H>>>(a0, ws + 1 * DD, bs + 1 * D_DIM,
                                       a1, nullptr, nullptr, nullptr);
    gemm_hid<0><<<grid, NTH, SMEM_H>>>(a1, ws + 2 * DD, bs + 2 * D_DIM,
                                       a0, nullptr, nullptr, nullptr);
    // Layer 4 + interaction fusion; A5 stored hi/lo (x16 reused as lo plane)
    gemm_hid<1><<<grid, NTH, SMEM_H>>>(a0, ws + 3 * DD, bs + 3 * D_DIM,
                                       a1, x16, x, rs);
    // Final projection: 3-term split fp16, fp32 out
    gemm_fin<<<grid, NTH, SMEM_F>>>(a1, x16, woh, wol, bo, out);
}